// round 9
// baseline (speedup 1.0000x reference)
#include <cuda_runtime.h>
#include <cuda_fp16.h>

#define N_NODES 100000
#define N_PAD   100032
#define K 32
#define D 64
#define CAP 96                   // per-dst bucket capacity (Poisson(32) tail ~1e-18)
#define NEG_SLOPE 0.2f

// Persistent scratch — replay-safe by invariant:
//   g_cnt starts zero (.bss) and is re-zeroed by k_gather every launch.
//   Everything else is fully rewritten every launch.
__device__ __align__(128) __half g_h16[(size_t)N_PAD * D];
__device__ float g_si[N_PAD];
__device__ float g_sj[N_PAD];
__device__ int   g_cnt[N_PAD];
__device__ __align__(128) int   g_bkt[(size_t)N_NODES * CAP];

// ---------------------------------------------------------------------------
// Kernel 1 (tensor-core): h = embed @ W via mma.sync.m16n8k16 (fp16 in,
// fp32 accum); si = h.a_i, sj = h.a_j in fp32 from c-fragments + quad shfl.
// 8 warps/block, 16 rows/warp -> 128 rows/block, grid 782.
// ---------------------------------------------------------------------------
__global__ void __launch_bounds__(256) k_gemm(const float* __restrict__ embed,
                                              const float* __restrict__ W,
                                              const float* __restrict__ att) {
    __shared__ unsigned sw2[32][72];   // 72-word stride: b-frag LDS conflict-free
    __shared__ float s_att[128];

    int t = threadIdx.x;
    int base = blockIdx.x * 128;

    for (int idx = t; idx < 32 * 64; idx += 256) {
        int kk = idx >> 6, n = idx & 63;
        __half2 h2 = __floats2half2_rn(__ldg(&W[(2 * kk) * 64 + n]),
                                       __ldg(&W[(2 * kk + 1) * 64 + n]));
        sw2[kk][n] = *reinterpret_cast<unsigned*>(&h2);
    }
    if (t < 128) s_att[t] = __ldg(&att[t]);
    __syncthreads();

    int lane = t & 31, w = t >> 5;
    int r0 = base + w * 16 + (lane >> 2);
    int r1 = r0 + 8;
    int kq = (lane & 3) * 2;

    unsigned a[4][4];
#pragma unroll
    for (int ks = 0; ks < 4; ks++) {
        int k = ks * 16 + kq;
        float2 f0 = (r0 < N_NODES) ? *reinterpret_cast<const float2*>(embed + (size_t)r0 * D + k)     : make_float2(0.f, 0.f);
        float2 f1 = (r1 < N_NODES) ? *reinterpret_cast<const float2*>(embed + (size_t)r1 * D + k)     : make_float2(0.f, 0.f);
        float2 f2 = (r0 < N_NODES) ? *reinterpret_cast<const float2*>(embed + (size_t)r0 * D + k + 8) : make_float2(0.f, 0.f);
        float2 f3 = (r1 < N_NODES) ? *reinterpret_cast<const float2*>(embed + (size_t)r1 * D + k + 8) : make_float2(0.f, 0.f);
        __half2 h;
        h = __floats2half2_rn(f0.x, f0.y); a[ks][0] = *reinterpret_cast<unsigned*>(&h);
        h = __floats2half2_rn(f1.x, f1.y); a[ks][1] = *reinterpret_cast<unsigned*>(&h);
        h = __floats2half2_rn(f2.x, f2.y); a[ks][2] = *reinterpret_cast<unsigned*>(&h);
        h = __floats2half2_rn(f3.x, f3.y); a[ks][3] = *reinterpret_cast<unsigned*>(&h);
    }

    int nb = lane >> 2;
    float psi0 = 0.f, psj0 = 0.f, psi1 = 0.f, psj1 = 0.f;

#pragma unroll
    for (int nt = 0; nt < 8; nt++) {
        float c0 = 0.f, c1 = 0.f, c2 = 0.f, c3 = 0.f;
#pragma unroll
        for (int ks = 0; ks < 4; ks++) {
            unsigned b0 = sw2[ks * 8 + (lane & 3)][nt * 8 + nb];
            unsigned b1 = sw2[ks * 8 + (lane & 3) + 4][nt * 8 + nb];
            asm volatile(
                "mma.sync.aligned.m16n8k16.row.col.f32.f16.f16.f32 "
                "{%0,%1,%2,%3}, {%4,%5,%6,%7}, {%8,%9}, {%0,%1,%2,%3};"
                : "+f"(c0), "+f"(c1), "+f"(c2), "+f"(c3)
                : "r"(a[ks][0]), "r"(a[ks][1]), "r"(a[ks][2]), "r"(a[ks][3]),
                  "r"(b0), "r"(b1));
        }
        int col = nt * 8 + kq;

        float ai0 = s_att[col],      ai1 = s_att[col + 1];
        float aj0 = s_att[64 + col], aj1 = s_att[64 + col + 1];
        psi0 += c0 * ai0 + c1 * ai1;
        psj0 += c0 * aj0 + c1 * aj1;
        psi1 += c2 * ai0 + c3 * ai1;
        psj1 += c2 * aj0 + c3 * aj1;

        __half2 h01 = __floats2half2_rn(c0, c1);
        __half2 h23 = __floats2half2_rn(c2, c3);
        if (r0 < N_NODES) *reinterpret_cast<__half2*>(g_h16 + (size_t)r0 * D + col) = h01;
        if (r1 < N_NODES) *reinterpret_cast<__half2*>(g_h16 + (size_t)r1 * D + col) = h23;
    }

#pragma unroll
    for (int o = 1; o <= 2; o <<= 1) {
        psi0 += __shfl_xor_sync(0xffffffffu, psi0, o);
        psj0 += __shfl_xor_sync(0xffffffffu, psj0, o);
        psi1 += __shfl_xor_sync(0xffffffffu, psi1, o);
        psj1 += __shfl_xor_sync(0xffffffffu, psj1, o);
    }
    if ((lane & 3) == 0) {
        if (r0 < N_NODES) { g_si[r0] = psi0; g_sj[r0] = psj0; }
        if (r1 < N_NODES) { g_si[r1] = psi1; g_sj[r1] = psj1; }
    }
}

// ---------------------------------------------------------------------------
// Kernel 2: PURE transpose — scatter src into per-dst buckets. No attention
// math here (e is computed vectorized in k_gather's staging phase), so the
// loop is just LDG -> ATOMG -> STG.32 with MLP=4.
// Relies on g_cnt == 0 at entry (zeroed by k_gather at end of prior launch).
// ---------------------------------------------------------------------------
__global__ void __launch_bounds__(256) k_fill(const int* __restrict__ edges) {
    int t = threadIdx.x;
    int base = blockIdx.x * 1024;             // 1024 edges per block

#pragma unroll
    for (int i = 0; i < 4; i++) {
        int j = base + i * 256 + t;           // coalesced edge index
        int src = j >> 5;
        int dst = __ldg(&edges[j]);
        if (dst != src) {                     // self K-edges are invalid
            int pos = atomicAdd(&g_cnt[dst], 1);
            if (pos < CAP)
                g_bkt[(size_t)dst * CAP + pos] = src;
        }
    }
}

// ---------------------------------------------------------------------------
// Kernel 3: gather + finalize. Warp per dst node.
// Stage: lanes compute e = exp(lrelu(si[dst]+sj[src])) for all bucket entries
//   in parallel (MLP-rich random 4B loads); self-loop is entry src=dst;
//   pads (e=0) round the list up to a multiple of 4.
// Main loop: 4 edges/iter, one per quarter-warp; lane owns 8 cols via one
//   LDG.128 of the fp16 row. Then quarter-merge, bias, L2-normalize, store.
// Re-zeroes g_cnt[dst] for the next launch.
// ---------------------------------------------------------------------------
__global__ void __launch_bounds__(256) k_gather(const float* __restrict__ bias,
                                                float* __restrict__ out) {
    __shared__ int2 sb[8][CAP + 4];

    int lane = threadIdx.x & 31;
    int w    = threadIdx.x >> 5;
    int q    = lane >> 3;        // quarter-warp id (edge slot within iter)
    int c8   = lane & 7;         // col group: 8 fp16 = 16B
    int dst  = blockIdx.x * 8 + w;

    int deg = min(g_cnt[dst], CAP);
    const int* bp = g_bkt + (size_t)dst * CAP;
    float si = __ldg(&g_si[dst]);

    // Stage (src, e); entry 'deg' is the self loop (src = dst).
    for (int j = lane; j <= deg; j += 32) {
        int s = dst;
        if (j < deg) s = __ldg(&bp[j]);
        float a = si + __ldg(&g_sj[s]);
        a = fmaxf(a, NEG_SLOPE * a);          // leaky relu
        sb[w][j] = make_int2(s, __float_as_int(__expf(a)));
    }
    int total = deg + 1;
    int iters = (total + 3) >> 2;
    for (int j = total + lane; j < 4 * iters; j += 32)
        sb[w][j] = make_int2(dst, 0);         // pad: e = 0
    if (lane == 0) g_cnt[dst] = 0;            // reset for next launch
    __syncwarp();

    float acc[8] = {0.f, 0.f, 0.f, 0.f, 0.f, 0.f, 0.f, 0.f};
    float den = 0.f;

#pragma unroll 2
    for (int j = 0; j < iters; j++) {
        int2 ent = sb[w][4 * j + q];          // 4 bcast addrs, distinct banks
        float e = __int_as_float(ent.y);
        uint4 u = reinterpret_cast<const uint4*>(g_h16 + (size_t)ent.x * D)[c8];
        float2 f0 = __half22float2(*reinterpret_cast<__half2*>(&u.x));
        float2 f1 = __half22float2(*reinterpret_cast<__half2*>(&u.y));
        float2 f2 = __half22float2(*reinterpret_cast<__half2*>(&u.z));
        float2 f3 = __half22float2(*reinterpret_cast<__half2*>(&u.w));
        acc[0] += f0.x * e; acc[1] += f0.y * e;
        acc[2] += f1.x * e; acc[3] += f1.y * e;
        acc[4] += f2.x * e; acc[5] += f2.y * e;
        acc[6] += f3.x * e; acc[7] += f3.y * e;
        den += e;
    }

    // Merge the 4 quarter-warp partials (cols duplicated across quarters).
#pragma unroll
    for (int o = 8; o <= 16; o <<= 1) {
#pragma unroll
        for (int i = 0; i < 8; i++)
            acc[i] += __shfl_xor_sync(0xffffffffu, acc[i], o);
        den += __shfl_xor_sync(0xffffffffu, den, o);
    }

    float4 b0 = __ldg(reinterpret_cast<const float4*>(bias) + 2 * c8);
    float4 b1 = __ldg(reinterpret_cast<const float4*>(bias) + 2 * c8 + 1);
    float inv = 1.f / (den + 1e-16f);
    float v[8];
    v[0] = acc[0] * inv + b0.x; v[1] = acc[1] * inv + b0.y;
    v[2] = acc[2] * inv + b0.z; v[3] = acc[3] * inv + b0.w;
    v[4] = acc[4] * inv + b1.x; v[5] = acc[5] * inv + b1.y;
    v[6] = acc[6] * inv + b1.z; v[7] = acc[7] * inv + b1.w;

    float ss = 0.f;
#pragma unroll
    for (int i = 0; i < 8; i++) ss += v[i] * v[i];
#pragma unroll
    for (int o = 1; o <= 4; o <<= 1)
        ss += __shfl_xor_sync(0xffffffffu, ss, o);

    float scale = 1.f / fmaxf(sqrtf(ss), 1e-12f);
    if (lane < 8) {
        float4* op = reinterpret_cast<float4*>(out + (size_t)dst * D) + 2 * c8;
        op[0] = make_float4(v[0] * scale, v[1] * scale, v[2] * scale, v[3] * scale);
        op[1] = make_float4(v[4] * scale, v[5] * scale, v[6] * scale, v[7] * scale);
    }
}

// ---------------------------------------------------------------------------
extern "C" void kernel_launch(void* const* d_in, const int* in_sizes, int n_in,
                              void* d_out, int out_size) {
    const float* embed = (const float*)d_in[0];
    const float* W     = (const float*)d_in[1];
    const float* att   = (const float*)d_in[2];
    const float* bias  = (const float*)d_in[3];
    const int*   edges = (const int*)d_in[7];
    float* out = (float*)d_out;

    k_fill  <<<(N_NODES * K) / 1024, 256>>>(edges);           // 3125 blocks
    k_gemm  <<<(N_NODES + 127) / 128, 256>>>(embed, W, att);  // 782 blocks
    k_gather<<<N_NODES / 8, 256>>>(bias, out);                // 12500 blocks
}

// round 10
// speedup vs baseline: 1.0785x; 1.0785x over previous
#include <cuda_runtime.h>
#include <cuda_fp16.h>

#define N_NODES 100000
#define N_PAD   100032
#define K 32
#define D 64
#define CAP_SUB 32               // per-sub-bucket capacity (Poisson(8) tail ~7e-11)
#define NEG_SLOPE 0.2f

#define GEMM_BLOCKS 782
#define FILL_BLOCKS 3125

// Persistent scratch — replay-safe by invariant:
//   g_cnt4 starts zero (.bss) and is re-zeroed by k_gather every launch.
//   Everything else is fully rewritten every launch.
__device__ __align__(128) __half g_h16[(size_t)N_PAD * D];
__device__ float g_si[N_PAD];
__device__ float g_sj[N_PAD];
__device__ int   g_cnt4[4][N_PAD];              // separate arrays: spread atomics
__device__ __align__(128) int g_bkt[(size_t)N_NODES * 4 * CAP_SUB];

// ---------------------------------------------------------------------------
// Kernel 1 (heterogeneous): bid%5==0 blocks run the tensor-core GEMM
// (h = embed @ W, si/sj in fp32 from c-frags); other blocks run the pure
// edge transpose (scatter src into 4-way sub-buckets keyed by src&3).
// The two workloads are independent; block-level mixing overlaps fill's
// L2-atomic latency with gemm's tensor/DRAM work.
// ---------------------------------------------------------------------------
__global__ void __launch_bounds__(256) k_gemm_fill(const float* __restrict__ embed,
                                                   const float* __restrict__ W,
                                                   const float* __restrict__ att,
                                                   const int* __restrict__ edges) {
    __shared__ unsigned sw2[32][72];   // 72-word stride: b-frag LDS conflict-free
    __shared__ float s_att[128];

    int bid = blockIdx.x;
    int t = threadIdx.x;

    if (bid % 5 != 0) {
        // ---------------- fill path: pure transpose ----------------
        int f = (bid / 5) * 4 + (bid % 5) - 1;
        if (f >= FILL_BLOCKS) return;
        int base = f * 1024;                  // 1024 edges per block
#pragma unroll
        for (int i = 0; i < 4; i++) {
            int j = base + i * 256 + t;       // coalesced edge index
            int src = j >> 5;                 // warp-uniform
            int dst = __ldg(&edges[j]);
            if (dst != src) {                 // self K-edges are invalid
                int sub = src & 3;            // warp-uniform sub-bucket
                int pos = atomicAdd(&g_cnt4[sub][dst], 1);
                if (pos < CAP_SUB)
                    g_bkt[(size_t)dst * (4 * CAP_SUB) + sub * CAP_SUB + pos] = src;
            }
        }
        return;
    }

    // ---------------- gemm path ----------------
    int gb = bid / 5;                         // 0..781
    int base = gb * 128;

    for (int idx = t; idx < 32 * 64; idx += 256) {
        int kk = idx >> 6, n = idx & 63;
        __half2 h2 = __floats2half2_rn(__ldg(&W[(2 * kk) * 64 + n]),
                                       __ldg(&W[(2 * kk + 1) * 64 + n]));
        sw2[kk][n] = *reinterpret_cast<unsigned*>(&h2);
    }
    if (t < 128) s_att[t] = __ldg(&att[t]);
    __syncthreads();

    int lane = t & 31, w = t >> 5;
    int r0 = base + w * 16 + (lane >> 2);
    int r1 = r0 + 8;
    int kq = (lane & 3) * 2;

    unsigned a[4][4];
#pragma unroll
    for (int ks = 0; ks < 4; ks++) {
        int k = ks * 16 + kq;
        float2 f0 = (r0 < N_NODES) ? *reinterpret_cast<const float2*>(embed + (size_t)r0 * D + k)     : make_float2(0.f, 0.f);
        float2 f1 = (r1 < N_NODES) ? *reinterpret_cast<const float2*>(embed + (size_t)r1 * D + k)     : make_float2(0.f, 0.f);
        float2 f2 = (r0 < N_NODES) ? *reinterpret_cast<const float2*>(embed + (size_t)r0 * D + k + 8) : make_float2(0.f, 0.f);
        float2 f3 = (r1 < N_NODES) ? *reinterpret_cast<const float2*>(embed + (size_t)r1 * D + k + 8) : make_float2(0.f, 0.f);
        __half2 h;
        h = __floats2half2_rn(f0.x, f0.y); a[ks][0] = *reinterpret_cast<unsigned*>(&h);
        h = __floats2half2_rn(f1.x, f1.y); a[ks][1] = *reinterpret_cast<unsigned*>(&h);
        h = __floats2half2_rn(f2.x, f2.y); a[ks][2] = *reinterpret_cast<unsigned*>(&h);
        h = __floats2half2_rn(f3.x, f3.y); a[ks][3] = *reinterpret_cast<unsigned*>(&h);
    }

    int nb = lane >> 2;
    float psi0 = 0.f, psj0 = 0.f, psi1 = 0.f, psj1 = 0.f;

#pragma unroll
    for (int nt = 0; nt < 8; nt++) {
        float c0 = 0.f, c1 = 0.f, c2 = 0.f, c3 = 0.f;
#pragma unroll
        for (int ks = 0; ks < 4; ks++) {
            unsigned b0 = sw2[ks * 8 + (lane & 3)][nt * 8 + nb];
            unsigned b1 = sw2[ks * 8 + (lane & 3) + 4][nt * 8 + nb];
            asm volatile(
                "mma.sync.aligned.m16n8k16.row.col.f32.f16.f16.f32 "
                "{%0,%1,%2,%3}, {%4,%5,%6,%7}, {%8,%9}, {%0,%1,%2,%3};"
                : "+f"(c0), "+f"(c1), "+f"(c2), "+f"(c3)
                : "r"(a[ks][0]), "r"(a[ks][1]), "r"(a[ks][2]), "r"(a[ks][3]),
                  "r"(b0), "r"(b1));
        }
        int col = nt * 8 + kq;

        float ai0 = s_att[col],      ai1 = s_att[col + 1];
        float aj0 = s_att[64 + col], aj1 = s_att[64 + col + 1];
        psi0 += c0 * ai0 + c1 * ai1;
        psj0 += c0 * aj0 + c1 * aj1;
        psi1 += c2 * ai0 + c3 * ai1;
        psj1 += c2 * aj0 + c3 * aj1;

        __half2 h01 = __floats2half2_rn(c0, c1);
        __half2 h23 = __floats2half2_rn(c2, c3);
        if (r0 < N_NODES) *reinterpret_cast<__half2*>(g_h16 + (size_t)r0 * D + col) = h01;
        if (r1 < N_NODES) *reinterpret_cast<__half2*>(g_h16 + (size_t)r1 * D + col) = h23;
    }

#pragma unroll
    for (int o = 1; o <= 2; o <<= 1) {
        psi0 += __shfl_xor_sync(0xffffffffu, psi0, o);
        psj0 += __shfl_xor_sync(0xffffffffu, psj0, o);
        psi1 += __shfl_xor_sync(0xffffffffu, psi1, o);
        psj1 += __shfl_xor_sync(0xffffffffu, psj1, o);
    }
    if ((lane & 3) == 0) {
        if (r0 < N_NODES) { g_si[r0] = psi0; g_sj[r0] = psj0; }
        if (r1 < N_NODES) { g_si[r1] = psi1; g_sj[r1] = psj1; }
    }
}

// ---------------------------------------------------------------------------
// Kernel 2: gather + finalize. Warp per dst node.
// Stage: concatenate the 4 sub-buckets into smem, computing
//   e = exp(lrelu(si[dst]+sj[src])) 32-wide; self-loop appended (src=dst);
//   pads (e=0) round up to a multiple of 4. Re-zeroes the 4 counters.
// Main loop: 4 edges/iter (one per quarter-warp); lane owns 8 cols via one
//   LDG.128 of the fp16 row. Quarter-merge, bias, L2-normalize, store.
// ---------------------------------------------------------------------------
__global__ void __launch_bounds__(256) k_gather(const float* __restrict__ bias,
                                                float* __restrict__ out) {
    __shared__ int2 sb[8][4 * CAP_SUB + 4];

    int lane = threadIdx.x & 31;
    int w    = threadIdx.x >> 5;
    int q    = lane >> 3;        // quarter-warp id (edge slot within iter)
    int c8   = lane & 7;         // col group: 8 fp16 = 16B
    int dst  = blockIdx.x * 8 + w;

    float si = __ldg(&g_si[dst]);

    // Counts of the 4 sub-buckets (warp-broadcast loads) + running offsets.
    int c0 = min(__ldg(&g_cnt4[0][dst]), CAP_SUB);
    int c1 = min(__ldg(&g_cnt4[1][dst]), CAP_SUB);
    int c2 = min(__ldg(&g_cnt4[2][dst]), CAP_SUB);
    int c3 = min(__ldg(&g_cnt4[3][dst]), CAP_SUB);
    int cs[4]  = {c0, c1, c2, c3};
    int off[4] = {0, c0, c0 + c1, c0 + c1 + c2};
    int deg = c0 + c1 + c2 + c3;

    const int* bp = g_bkt + (size_t)dst * (4 * CAP_SUB);
#pragma unroll
    for (int s = 0; s < 4; s++) {
        if (lane < cs[s]) {                       // cs[s] <= 32: single round
            int src = __ldg(&bp[s * CAP_SUB + lane]);
            float a = si + __ldg(&g_sj[src]);
            a = fmaxf(a, NEG_SLOPE * a);          // leaky relu
            sb[w][off[s] + lane] = make_int2(src, __float_as_int(__expf(a)));
        }
    }
    if (lane < 4) g_cnt4[lane][dst] = 0;          // reset for next launch

    // Self loop at index deg; pads (e=0) up to multiple of 4.
    if (lane == 0) {
        float a = si + g_sj[dst];
        a = fmaxf(a, NEG_SLOPE * a);
        sb[w][deg] = make_int2(dst, __float_as_int(__expf(a)));
    }
    int total = deg + 1;
    int iters = (total + 3) >> 2;
    if (lane >= total - 4 * (iters - 1) && lane < 4)   // remaining pad slots
        sb[w][4 * (iters - 1) + lane] = make_int2(dst, 0);
    __syncwarp();

    float acc[8] = {0.f, 0.f, 0.f, 0.f, 0.f, 0.f, 0.f, 0.f};
    float den = 0.f;

#pragma unroll 2
    for (int j = 0; j < iters; j++) {
        int2 ent = sb[w][4 * j + q];          // 4 bcast addrs, distinct banks
        float e = __int_as_float(ent.y);
        uint4 u = reinterpret_cast<const uint4*>(g_h16 + (size_t)ent.x * D)[c8];
        float2 f0 = __half22float2(*reinterpret_cast<__half2*>(&u.x));
        float2 f1 = __half22float2(*reinterpret_cast<__half2*>(&u.y));
        float2 f2 = __half22float2(*reinterpret_cast<__half2*>(&u.z));
        float2 f3 = __half22float2(*reinterpret_cast<__half2*>(&u.w));
        acc[0] += f0.x * e; acc[1] += f0.y * e;
        acc[2] += f1.x * e; acc[3] += f1.y * e;
        acc[4] += f2.x * e; acc[5] += f2.y * e;
        acc[6] += f3.x * e; acc[7] += f3.y * e;
        den += e;
    }

    // Merge the 4 quarter-warp partials (cols duplicated across quarters).
#pragma unroll
    for (int o = 8; o <= 16; o <<= 1) {
#pragma unroll
        for (int i = 0; i < 8; i++)
            acc[i] += __shfl_xor_sync(0xffffffffu, acc[i], o);
        den += __shfl_xor_sync(0xffffffffu, den, o);
    }

    float4 b0 = __ldg(reinterpret_cast<const float4*>(bias) + 2 * c8);
    float4 b1 = __ldg(reinterpret_cast<const float4*>(bias) + 2 * c8 + 1);
    float inv = 1.f / (den + 1e-16f);
    float v[8];
    v[0] = acc[0] * inv + b0.x; v[1] = acc[1] * inv + b0.y;
    v[2] = acc[2] * inv + b0.z; v[3] = acc[3] * inv + b0.w;
    v[4] = acc[4] * inv + b1.x; v[5] = acc[5] * inv + b1.y;
    v[6] = acc[6] * inv + b1.z; v[7] = acc[7] * inv + b1.w;

    float ss = 0.f;
#pragma unroll
    for (int i = 0; i < 8; i++) ss += v[i] * v[i];
#pragma unroll
    for (int o = 1; o <= 4; o <<= 1)
        ss += __shfl_xor_sync(0xffffffffu, ss, o);

    float scale = 1.f / fmaxf(sqrtf(ss), 1e-12f);
    if (lane < 8) {
        float4* op = reinterpret_cast<float4*>(out + (size_t)dst * D) + 2 * c8;
        op[0] = make_float4(v[0] * scale, v[1] * scale, v[2] * scale, v[3] * scale);
        op[1] = make_float4(v[4] * scale, v[5] * scale, v[6] * scale, v[7] * scale);
    }
}

// ---------------------------------------------------------------------------
extern "C" void kernel_launch(void* const* d_in, const int* in_sizes, int n_in,
                              void* d_out, int out_size) {
    const float* embed = (const float*)d_in[0];
    const float* W     = (const float*)d_in[1];
    const float* att   = (const float*)d_in[2];
    const float* bias  = (const float*)d_in[3];
    const int*   edges = (const int*)d_in[7];
    float* out = (float*)d_out;

    k_gemm_fill<<<GEMM_BLOCKS * 5, 256>>>(embed, W, att, edges);  // 3910 blocks
    k_gather   <<<N_NODES / 8, 256>>>(bias, out);                 // 12500 blocks
}